// round 1
// baseline (speedup 1.0000x reference)
#include <cuda_runtime.h>
#include <stdint.h>

#define Bn 64
#define Cc 64
#define Hh 56
#define Ww 56
#define Pp 64
#define HW (Hh*Ww)        // 3136
#define CHW (Cc*HW)       // 200704
#define PIX (Bn*HW)       // 200704
#define PADW 58
#define PADHW (58*58)     // 3364
#define NPIX 4
#define GPR (Ww/NPIX)     // 14
#define GROUPS (PIX/NPIX) // 50176

// ---- device scratch (statically zero-initialized; border of g_amask stays 0) ----
__device__ unsigned long long g_amask[Bn*PADHW];   // padded per-pixel sign masks (~1.7MB)
__device__ uint4  g_wm[Pp*9];                      // per (p,tap): pw_lo,pw_hi,nw_lo,nw_hi
__device__ int    g_basec[9*Pp];                   // per (border-case, p): base constant
__device__ float4 g_epi[Pp];                       // A=scale*inv, Bc=beta-mean*inv+bias1, alpha, bias2
__device__ int    g_zero_cnt;
__device__ int    g_zero_list[4096];

// ---------------- prep: weight masks + fused epilogue constants ----------------
__global__ void prep_kernel(const float* __restrict__ w,
                            const float* __restrict__ gamma,
                            const float* __restrict__ beta,
                            const float* __restrict__ rmean,
                            const float* __restrict__ rvar,
                            const float* __restrict__ bias1,
                            const float* __restrict__ alpha,
                            const float* __restrict__ bias2) {
    int p = threadIdx.x;
    if (p == 0) g_zero_cnt = 0;
    if (p >= Pp) return;

    unsigned long long pw[9], nw[9];
    #pragma unroll
    for (int t = 0; t < 9; t++) { pw[t] = 0ull; nw[t] = 0ull; }
    float sabs = 0.f;
    const float* wp = w + p * (Cc*9);
    for (int c = 0; c < Cc; c++) {
        #pragma unroll
        for (int t = 0; t < 9; t++) {
            float wv = wp[c*9 + t];
            sabs += fabsf(wv);
            if (wv > 0.f)      pw[t] |= 1ull << c;
            else if (wv < 0.f) nw[t] |= 1ull << c;
        }
    }
    float scale = sabs * (1.0f / (float)(Cc*9));

    int nwt[9], cnw[9];
    #pragma unroll
    for (int t = 0; t < 9; t++) {
        nwt[t] = __popcll(pw[t] | nw[t]);
        cnw[t] = __popcll(nw[t]);
        uint4 v;
        v.x = (unsigned)(pw[t]);       v.y = (unsigned)(pw[t] >> 32);
        v.z = (unsigned)(nw[t]);       v.w = (unsigned)(nw[t] >> 32);
        g_wm[p*9 + t] = v;
    }
    // Border-case base constants: conv = base[case] - 2*acc, where invalid
    // (padded) taps see sa=0 so their popc contribution is popc(nw)=cnw.
    for (int cs = 0; cs < 9; cs++) {
        int ch = cs / 3, cw = cs % 3;
        int base = 0;
        #pragma unroll
        for (int t = 0; t < 9; t++) {
            int kh = t / 3, kw = t % 3;
            bool invalid = (ch==0 && kh==0) || (ch==2 && kh==2) ||
                           (cw==0 && kw==0) || (cw==2 && kw==2);
            base += invalid ? 2*cnw[t] : nwt[t];
        }
        g_basec[cs*Pp + p] = base;
    }
    float inv = gamma[p] / sqrtf(rvar[p] + 1e-5f);
    float4 e;
    e.x = scale * inv;
    e.y = beta[p] - rmean[p]*inv + bias1[p];
    e.z = alpha[p];
    e.w = bias2[p];
    g_epi[p] = e;
}

// ---------------- binarize: pack channel sign bits per pixel ----------------
__global__ void binarize_kernel(const float* __restrict__ x,
                                const float* __restrict__ bias0) {
    int tid = blockIdx.x*blockDim.x + threadIdx.x;
    if (tid >= PIX) return;
    int b = tid / HW;
    int r = tid % HW;
    const float* xp = x + (size_t)b*CHW + r;
    unsigned lo = 0, hi = 0;
    #pragma unroll 8
    for (int c = 0; c < Cc; c++) {
        float v = __ldg(xp + (size_t)c*HW) + __ldg(bias0 + c);
        unsigned bit = (v < 0.f) ? 1u : 0u;
        if (c < 32) lo |= bit << c;
        else        hi |= bit << (c - 32);
        if (v == 0.f) {  // exact zero -> sign()==0; queue for exact fixup
            int s = atomicAdd(&g_zero_cnt, 1);
            if (s < 4096) g_zero_list[s] = b*CHW + c*HW + r;
        }
    }
    int h = r / Ww, w_ = r % Ww;
    g_amask[b*PADHW + (h+1)*PADW + (w_+1)] =
        (unsigned long long)lo | ((unsigned long long)hi << 32);
}

// ---------------- conv: popcount ternary conv + fused epilogue ----------------
__global__ __launch_bounds__(128)
void conv_kernel(const float* __restrict__ x, float* __restrict__ out) {
    __shared__ uint4  s_wm[Pp*9];
    __shared__ int    s_base[9*Pp];
    __shared__ float4 s_epi[Pp];
    for (int i = threadIdx.x; i < Pp*9; i += blockDim.x) s_wm[i]   = g_wm[i];
    for (int i = threadIdx.x; i < 9*Pp; i += blockDim.x) s_base[i] = g_basec[i];
    for (int i = threadIdx.x; i < Pp;   i += blockDim.x) s_epi[i]  = g_epi[i];
    __syncthreads();

    int g = blockIdx.x*blockDim.x + threadIdx.x;
    if (g >= GROUPS) return;
    int b  = g / (Hh*GPR);
    int r  = g % (Hh*GPR);
    int h  = r / GPR;
    int w0 = (r % GPR) * NPIX;

    // 3 rows x 6 cols of padded neighbor masks (covers 4 output pixels)
    unsigned long long m[3][6];
    const unsigned long long* am = g_amask + b*PADHW;
    #pragma unroll
    for (int ri = 0; ri < 3; ri++)
        #pragma unroll
        for (int ci = 0; ci < 6; ci++)
            m[ri][ci] = am[(h+ri)*PADW + (w0+ci)];

    int ch    = (h == 0) ? 0 : ((h == Hh-1) ? 2 : 1);
    int caseM = ch*3 + 1;
    int caseL = ch*3 + ((w0 == 0) ? 0 : 1);
    int caseR = ch*3 + ((w0 + NPIX - 1 == Ww-1) ? 2 : 1);

    size_t obase = (size_t)b*CHW + (size_t)h*Ww + w0;

    for (int p = 0; p < Pp; p++) {
        int acc0 = 0, acc1 = 0, acc2 = 0, acc3 = 0;
        #pragma unroll
        for (int t = 0; t < 9; t++) {
            uint4 wv = s_wm[p*9 + t];
            const int ri = t / 3, ci = t % 3;
            {
                unsigned long long sa = m[ri][ci+0];
                unsigned slo = (unsigned)sa, shi = (unsigned)(sa >> 32);
                acc0 += __popc((wv.x & slo) | (wv.z & ~slo))
                      + __popc((wv.y & shi) | (wv.w & ~shi));
            }
            {
                unsigned long long sa = m[ri][ci+1];
                unsigned slo = (unsigned)sa, shi = (unsigned)(sa >> 32);
                acc1 += __popc((wv.x & slo) | (wv.z & ~slo))
                      + __popc((wv.y & shi) | (wv.w & ~shi));
            }
            {
                unsigned long long sa = m[ri][ci+2];
                unsigned slo = (unsigned)sa, shi = (unsigned)(sa >> 32);
                acc2 += __popc((wv.x & slo) | (wv.z & ~slo))
                      + __popc((wv.y & shi) | (wv.w & ~shi));
            }
            {
                unsigned long long sa = m[ri][ci+3];
                unsigned slo = (unsigned)sa, shi = (unsigned)(sa >> 32);
                acc3 += __popc((wv.x & slo) | (wv.z & ~slo))
                      + __popc((wv.y & shi) | (wv.w & ~shi));
            }
        }
        int baseM = s_base[caseM*Pp + p];
        int baseL = s_base[caseL*Pp + p];
        int baseR = s_base[caseR*Pp + p];
        float4 e   = s_epi[p];
        float4 res = *(const float4*)(x + obase + (size_t)p*HW);

        float c0 = (float)(baseL - 2*acc0);
        float c1 = (float)(baseM - 2*acc1);
        float c2 = (float)(baseM - 2*acc2);
        float c3 = (float)(baseR - 2*acc3);

        float4 o;
        float v;
        v = fmaf(c0, e.x, e.y) + res.x; o.x = (v >= 0.f ? v : v*e.z) + e.w;
        v = fmaf(c1, e.x, e.y) + res.y; o.y = (v >= 0.f ? v : v*e.z) + e.w;
        v = fmaf(c2, e.x, e.y) + res.z; o.z = (v >= 0.f ? v : v*e.z) + e.w;
        v = fmaf(c3, e.x, e.y) + res.w; o.w = (v >= 0.f ? v : v*e.z) + e.w;
        *(float4*)(out + obase + (size_t)p*HW) = o;
    }
}

// ---------------- fixup: exact recompute for exact-zero activations ----------------
__global__ void fixup_kernel(const float* __restrict__ x,
                             const float* __restrict__ bias0,
                             const float* __restrict__ w,
                             float* __restrict__ out) {
    int cnt = g_zero_cnt;
    if (cnt > 4096) cnt = 4096;
    int nitems = cnt * 9 * Pp;
    for (int it = blockIdx.x*blockDim.x + threadIdx.x; it < nitems;
         it += gridDim.x*blockDim.x) {
        int zi  = it / (9*Pp);
        int rem = it % (9*Pp);
        int d   = rem / Pp;
        int p   = rem % Pp;
        int z   = g_zero_list[zi];
        int b   = z / CHW;
        int zr  = (z % CHW) % HW;
        int zh  = zr / Ww, zw = zr % Ww;
        int oh  = zh + (d/3) - 1;
        int ow  = zw + (d%3) - 1;
        if (oh < 0 || oh >= Hh || ow < 0 || ow >= Ww) continue;

        float conv = 0.f;
        const float* wp = w + p*(Cc*9);
        for (int c = 0; c < Cc; c++) {
            const float* xc = x + (size_t)b*CHW + (size_t)c*HW;
            float b0 = bias0[c];
            #pragma unroll
            for (int t = 0; t < 9; t++) {
                int ih = oh + t/3 - 1, iw = ow + t%3 - 1;
                if (ih < 0 || ih >= Hh || iw < 0 || iw >= Ww) continue;
                float v  = xc[ih*Ww + iw] + b0;
                float a  = (v  > 0.f) ? 1.f : ((v  < 0.f) ? -1.f : 0.f);
                float wv = wp[c*9 + t];
                float ws = (wv > 0.f) ? 1.f : ((wv < 0.f) ? -1.f : 0.f);
                conv += a * ws;
            }
        }
        float4 e = g_epi[p];
        size_t oi = (size_t)b*CHW + (size_t)p*HW + (size_t)oh*Ww + ow;
        float val = fmaf(conv, e.x, e.y) + x[oi];
        val = (val >= 0.f ? val : val*e.z) + e.w;
        out[oi] = val;
    }
}

// ---------------- launch ----------------
extern "C" void kernel_launch(void* const* d_in, const int* in_sizes, int n_in,
                              void* d_out, int out_size) {
    const float* x     = (const float*)d_in[0];
    const float* bias0 = (const float*)d_in[1];
    const float* w     = (const float*)d_in[2];
    const float* gamma = (const float*)d_in[3];
    const float* beta  = (const float*)d_in[4];
    const float* rmean = (const float*)d_in[5];
    const float* rvar  = (const float*)d_in[6];
    const float* bias1 = (const float*)d_in[7];
    const float* alpha = (const float*)d_in[8];
    const float* bias2 = (const float*)d_in[9];
    float* out = (float*)d_out;

    prep_kernel<<<1, 64>>>(w, gamma, beta, rmean, rvar, bias1, alpha, bias2);
    binarize_kernel<<<(PIX + 255)/256, 256>>>(x, bias0);
    conv_kernel<<<(GROUPS + 127)/128, 128>>>(x, out);
    fixup_kernel<<<64, 128>>>(x, bias0, w, out);
}

// round 2
// speedup vs baseline: 1.1054x; 1.1054x over previous
#include <cuda_runtime.h>
#include <stdint.h>

#define Bn 64
#define Cc 64
#define Hh 56
#define Ww 56
#define Pp 64
#define HW (Hh*Ww)        // 3136
#define CHW (Cc*HW)       // 200704
#define PIX (Bn*HW)       // 200704
#define PADW 58
#define PADHW (58*58)     // 3364
#define NPIX 4
#define GPR (Ww/NPIX)     // 14
#define GROUPS (PIX/NPIX) // 50176
#define PSPLIT 4
#define PPT (Pp/PSPLIT)   // 16 output channels per thread

// ---- device scratch (statically zero-initialized; border of g_amask stays 0) ----
__device__ unsigned long long g_amask[Bn*PADHW];   // padded per-pixel sign masks (~1.7MB)
__device__ uint4  g_wm[Pp*9];     // per (p,tap): pw_lo, pw_hi, vm_lo, vm_hi
__device__ float  g_basef[9*Pp];  // per (border-case, p): base constant (as float)
__device__ float4 g_epi[Pp];      // A=scale*inv, B=beta-mean*inv+bias1, alpha, bias2
__device__ int    g_zero_cnt;
__device__ int    g_zero_list[4096];

// ---------------- prep: weight masks + fused epilogue constants ----------------
__global__ void prep_kernel(const float* __restrict__ w,
                            const float* __restrict__ gamma,
                            const float* __restrict__ beta,
                            const float* __restrict__ rmean,
                            const float* __restrict__ rvar,
                            const float* __restrict__ bias1,
                            const float* __restrict__ alpha,
                            const float* __restrict__ bias2) {
    int p = threadIdx.x;
    if (p == 0) g_zero_cnt = 0;
    if (p >= Pp) return;

    unsigned long long pw[9], vm[9];
    #pragma unroll
    for (int t = 0; t < 9; t++) { pw[t] = 0ull; vm[t] = 0ull; }
    float sabs = 0.f;
    const float4* wp4 = (const float4*)(w + p * (Cc*9));
    #pragma unroll 4
    for (int i = 0; i < (Cc*9)/4; i++) {
        float4 v4 = __ldg(wp4 + i);
        float vv[4] = {v4.x, v4.y, v4.z, v4.w};
        #pragma unroll
        for (int k = 0; k < 4; k++) {
            int idx = 4*i + k;
            int c = idx / 9, t = idx % 9;
            float wv = vv[k];
            sabs += fabsf(wv);
            if (wv > 0.f) pw[t] |= 1ull << c;
            if (wv != 0.f) vm[t] |= 1ull << c;
        }
    }
    float scale = sabs * (1.0f / (float)(Cc*9));

    int nv[9], ppw[9];
    #pragma unroll
    for (int t = 0; t < 9; t++) {
        nv[t]  = __popcll(vm[t]);
        ppw[t] = __popcll(pw[t]);
        uint4 v;
        v.x = (unsigned)(pw[t]);  v.y = (unsigned)(pw[t] >> 32);
        v.z = (unsigned)(vm[t]);  v.w = (unsigned)(vm[t] >> 32);
        g_wm[p*9 + t] = v;
    }
    // conv = 2*acc - base[case], acc computed over all 9 taps with padded s=0.
    // valid tap contributes nv; invalid (padded) tap contributes 2*popc(pw).
    for (int cs = 0; cs < 9; cs++) {
        int ch = cs / 3, cw = cs % 3;
        int base = 0;
        #pragma unroll
        for (int t = 0; t < 9; t++) {
            int kh = t / 3, kw = t % 3;
            bool invalid = (ch==0 && kh==0) || (ch==2 && kh==2) ||
                           (cw==0 && kw==0) || (cw==2 && kw==2);
            base += invalid ? 2*ppw[t] : nv[t];
        }
        g_basef[cs*Pp + p] = (float)base;
    }
    float inv = gamma[p] / sqrtf(rvar[p] + 1e-5f);
    float4 e;
    e.x = scale * inv;
    e.y = beta[p] - rmean[p]*inv + bias1[p];
    e.z = alpha[p];
    e.w = bias2[p];
    g_epi[p] = e;
}

// ---------------- binarize: pack channel sign bits per pixel ----------------
__global__ void binarize_kernel(const float* __restrict__ x,
                                const float* __restrict__ bias0) {
    int tid = blockIdx.x*blockDim.x + threadIdx.x;
    if (tid >= PIX) return;
    int b = tid / HW;
    int r = tid % HW;
    const float* xp = x + (size_t)b*CHW + r;
    unsigned lo = 0, hi = 0;
    #pragma unroll 8
    for (int c = 0; c < Cc; c++) {
        float v = __ldg(xp + (size_t)c*HW) + __ldg(bias0 + c);
        unsigned bit = (v < 0.f) ? 1u : 0u;
        if (c < 32) lo |= bit << c;
        else        hi |= bit << (c - 32);
        if (v == 0.f) {  // exact zero -> sign()==0; queue for exact fixup
            int s = atomicAdd(&g_zero_cnt, 1);
            if (s < 4096) g_zero_list[s] = b*CHW + c*HW + r;
        }
    }
    int h = r / Ww, w_ = r % Ww;
    g_amask[b*PADHW + (h+1)*PADW + (w_+1)] =
        (unsigned long long)lo | ((unsigned long long)hi << 32);
}

// ---------------- conv: popcount ternary conv + fused epilogue ----------------
// Each thread: 4 horizontal pixels x 16 output channels (psub selects which 16).
__global__ __launch_bounds__(128)
void conv_kernel(const float* __restrict__ x, float* __restrict__ out) {
    __shared__ uint4  s_wm[Pp*9];
    __shared__ float  s_basef[9*Pp];
    __shared__ float4 s_epi[Pp];
    for (int i = threadIdx.x; i < Pp*9; i += blockDim.x) s_wm[i]    = g_wm[i];
    for (int i = threadIdx.x; i < 9*Pp; i += blockDim.x) s_basef[i] = g_basef[i];
    for (int i = threadIdx.x; i < Pp;   i += blockDim.x) s_epi[i]   = g_epi[i];
    __syncthreads();

    int tid  = blockIdx.x*blockDim.x + threadIdx.x;
    int g    = tid / PSPLIT;
    int psub = tid % PSPLIT;
    if (g >= GROUPS) return;
    int b  = g / (Hh*GPR);
    int r  = g % (Hh*GPR);
    int h  = r / GPR;
    int w0 = (r % GPR) * NPIX;

    // 3 rows x 6 cols of padded neighbor masks (covers 4 output pixels)
    unsigned long long m[3][6];
    const unsigned long long* am = g_amask + b*PADHW;
    #pragma unroll
    for (int ri = 0; ri < 3; ri++)
        #pragma unroll
        for (int ci = 0; ci < 6; ci++)
            m[ri][ci] = __ldg(am + (h+ri)*PADW + (w0+ci));

    int ch    = (h == 0) ? 0 : ((h == Hh-1) ? 2 : 1);
    int caseM = ch*3 + 1;
    int caseL = ch*3 + ((w0 == 0) ? 0 : 1);
    int caseR = ch*3 + ((w0 + NPIX - 1 == Ww-1) ? 2 : 1);

    size_t obase = (size_t)b*CHW + (size_t)h*Ww + w0;
    int p0 = psub * PPT;

    #pragma unroll 1
    for (int i = 0; i < PPT; i++) {
        int p = p0 + i;
        int acc0 = 0, acc1 = 0, acc2 = 0, acc3 = 0;
        #pragma unroll
        for (int t = 0; t < 9; t++) {
            uint4 wv = s_wm[p*9 + t];     // pw_lo, pw_hi, vm_lo, vm_hi
            const int ri = t / 3, ci = t % 3;
            {
                unsigned long long sa = m[ri][ci+0];
                acc0 += __popc(((unsigned)sa ^ wv.x) & wv.z)
                      + __popc(((unsigned)(sa>>32) ^ wv.y) & wv.w);
            }
            {
                unsigned long long sa = m[ri][ci+1];
                acc1 += __popc(((unsigned)sa ^ wv.x) & wv.z)
                      + __popc(((unsigned)(sa>>32) ^ wv.y) & wv.w);
            }
            {
                unsigned long long sa = m[ri][ci+2];
                acc2 += __popc(((unsigned)sa ^ wv.x) & wv.z)
                      + __popc(((unsigned)(sa>>32) ^ wv.y) & wv.w);
            }
            {
                unsigned long long sa = m[ri][ci+3];
                acc3 += __popc(((unsigned)sa ^ wv.x) & wv.z)
                      + __popc(((unsigned)(sa>>32) ^ wv.y) & wv.w);
            }
        }
        float4 e = s_epi[p];
        float A2 = 2.0f * e.x;
        float bM = fmaf(s_basef[caseM*Pp + p], -e.x, e.y);
        float bL = fmaf(s_basef[caseL*Pp + p], -e.x, e.y);
        float bR = fmaf(s_basef[caseR*Pp + p], -e.x, e.y);
        float4 res = *(const float4*)(x + obase + (size_t)p*HW);

        float4 o; float v;
        v = fmaf((float)acc0, A2, bL) + res.x; o.x = (v >= 0.f ? v : v*e.z) + e.w;
        v = fmaf((float)acc1, A2, bM) + res.y; o.y = (v >= 0.f ? v : v*e.z) + e.w;
        v = fmaf((float)acc2, A2, bM) + res.z; o.z = (v >= 0.f ? v : v*e.z) + e.w;
        v = fmaf((float)acc3, A2, bR) + res.w; o.w = (v >= 0.f ? v : v*e.z) + e.w;
        *(float4*)(out + obase + (size_t)p*HW) = o;
    }
}

// ---------------- fixup: exact recompute for exact-zero activations ----------------
__global__ void fixup_kernel(const float* __restrict__ x,
                             const float* __restrict__ bias0,
                             const float* __restrict__ w,
                             float* __restrict__ out) {
    int cnt = g_zero_cnt;
    if (cnt > 4096) cnt = 4096;
    int nitems = cnt * 9 * Pp;
    for (int it = blockIdx.x*blockDim.x + threadIdx.x; it < nitems;
         it += gridDim.x*blockDim.x) {
        int zi  = it / (9*Pp);
        int rem = it % (9*Pp);
        int d   = rem / Pp;
        int p   = rem % Pp;
        int z   = g_zero_list[zi];
        int b   = z / CHW;
        int zr  = (z % CHW) % HW;
        int zh  = zr / Ww, zw = zr % Ww;
        int oh  = zh + (d/3) - 1;
        int ow  = zw + (d%3) - 1;
        if (oh < 0 || oh >= Hh || ow < 0 || ow >= Ww) continue;

        float conv = 0.f;
        const float* wp = w + p*(Cc*9);
        for (int c = 0; c < Cc; c++) {
            const float* xc = x + (size_t)b*CHW + (size_t)c*HW;
            float b0 = bias0[c];
            #pragma unroll
            for (int t = 0; t < 9; t++) {
                int ih = oh + t/3 - 1, iw = ow + t%3 - 1;
                if (ih < 0 || ih >= Hh || iw < 0 || iw >= Ww) continue;
                float v  = xc[ih*Ww + iw] + b0;
                float a  = (v  > 0.f) ? 1.f : ((v  < 0.f) ? -1.f : 0.f);
                float wv = wp[c*9 + t];
                float ws = (wv > 0.f) ? 1.f : ((wv < 0.f) ? -1.f : 0.f);
                conv += a * ws;
            }
        }
        float4 e = g_epi[p];
        size_t oi = (size_t)b*CHW + (size_t)p*HW + (size_t)oh*Ww + ow;
        float val = fmaf(conv, e.x, e.y) + x[oi];
        val = (val >= 0.f ? val : val*e.z) + e.w;
        out[oi] = val;
    }
}

// ---------------- launch ----------------
extern "C" void kernel_launch(void* const* d_in, const int* in_sizes, int n_in,
                              void* d_out, int out_size) {
    const float* x     = (const float*)d_in[0];
    const float* bias0 = (const float*)d_in[1];
    const float* w     = (const float*)d_in[2];
    const float* gamma = (const float*)d_in[3];
    const float* beta  = (const float*)d_in[4];
    const float* rmean = (const float*)d_in[5];
    const float* rvar  = (const float*)d_in[6];
    const float* bias1 = (const float*)d_in[7];
    const float* alpha = (const float*)d_in[8];
    const float* bias2 = (const float*)d_in[9];
    float* out = (float*)d_out;

    prep_kernel<<<1, 64>>>(w, gamma, beta, rmean, rvar, bias1, alpha, bias2);
    binarize_kernel<<<(PIX + 255)/256, 256>>>(x, bias0);
    conv_kernel<<<(GROUPS*PSPLIT + 127)/128, 128>>>(x, out);
    fixup_kernel<<<64, 128>>>(x, bias0, w, out);
}

// round 3
// speedup vs baseline: 1.6052x; 1.4522x over previous
#include <cuda_runtime.h>
#include <stdint.h>

#define Bn 64
#define Cc 64
#define Hh 56
#define Ww 56
#define Pp 64
#define HW (Hh*Ww)        // 3136
#define CHW (Cc*HW)       // 200704
#define PIX (Bn*HW)       // 200704
#define PADW 58
#define PADHW (58*58)     // 3364
#define NPIX 4
#define GPR (Ww/NPIX)     // 14
#define GROUPS (PIX/NPIX) // 50176  (= 32 * 1568 exactly)
#define PSPLIT 4
#define PPT (Pp/PSPLIT)   // 16 output channels per thread

// ---- device scratch (statically zero-initialized; border of g_amask stays 0) ----
__device__ unsigned long long g_amask[Bn*PADHW];   // padded per-pixel sign masks (~1.7MB)
__device__ uint4  g_wm[Pp*9];     // per (p,tap): pw_lo, pw_hi, vm_lo, vm_hi
__device__ float  g_basef[9*Pp];  // per (border-case, p): base constant (as float)
__device__ float4 g_epi[Pp];      // A=scale*inv, B=beta-mean*inv+bias1, alpha, bias2
__device__ int    g_zero_cnt;
__device__ int    g_zero_list[4096];

// ---------------- prep: one block per output channel p; ballot-built masks ----------------
__global__ void prep_kernel(const float* __restrict__ w,
                            const float* __restrict__ gamma,
                            const float* __restrict__ beta,
                            const float* __restrict__ rmean,
                            const float* __restrict__ rvar,
                            const float* __restrict__ bias1,
                            const float* __restrict__ alpha,
                            const float* __restrict__ bias2) {
    int p = blockIdx.x;
    int c = threadIdx.x;            // 0..63 (one input channel per thread)
    int lane = c & 31, half = c >> 5;
    if (p == 0 && c == 0) g_zero_cnt = 0;

    __shared__ unsigned s_pw[2][9], s_vm[2][9];
    __shared__ float s_abs[64];

    const float* wp = w + (size_t)p*(Cc*9) + (size_t)c*9;
    float wv[9], sa = 0.f;
    #pragma unroll
    for (int t = 0; t < 9; t++) { wv[t] = __ldg(wp + t); sa += fabsf(wv[t]); }
    s_abs[c] = sa;
    #pragma unroll
    for (int t = 0; t < 9; t++) {
        unsigned bp = __ballot_sync(0xffffffffu, wv[t] > 0.f);
        unsigned bv = __ballot_sync(0xffffffffu, wv[t] != 0.f);
        if (lane == 0) { s_pw[half][t] = bp; s_vm[half][t] = bv; }
    }
    __syncthreads();
    if (c != 0) return;

    float sabs = 0.f;
    for (int i = 0; i < 64; i++) sabs += s_abs[i];
    float scale = sabs * (1.0f / (float)(Cc*9));

    int nv[9], ppw[9];
    #pragma unroll
    for (int t = 0; t < 9; t++) {
        uint4 v;
        v.x = s_pw[0][t]; v.y = s_pw[1][t];
        v.z = s_vm[0][t]; v.w = s_vm[1][t];
        g_wm[p*9 + t] = v;
        nv[t]  = __popc(v.z) + __popc(v.w);
        ppw[t] = __popc(v.x) + __popc(v.y);
    }
    // conv = 2*acc - base[case]; valid tap contributes nv, padded tap 2*popc(pw)
    #pragma unroll
    for (int cs = 0; cs < 9; cs++) {
        int ch = cs / 3, cw = cs % 3;
        int base = 0;
        #pragma unroll
        for (int t = 0; t < 9; t++) {
            int kh = t / 3, kw = t % 3;
            bool invalid = (ch==0 && kh==0) || (ch==2 && kh==2) ||
                           (cw==0 && kw==0) || (cw==2 && kw==2);
            base += invalid ? 2*ppw[t] : nv[t];
        }
        g_basef[cs*Pp + p] = (float)base;
    }
    float inv = gamma[p] / sqrtf(rvar[p] + 1e-5f);
    float4 e;
    e.x = scale * inv;
    e.y = beta[p] - rmean[p]*inv + bias1[p];
    e.z = alpha[p];
    e.w = bias2[p];
    g_epi[p] = e;
}

// ---------------- binarize: 4 pixels per thread via float4 ----------------
__global__ void binarize_kernel(const float* __restrict__ x,
                                const float* __restrict__ bias0) {
    int tid = blockIdx.x*blockDim.x + threadIdx.x;
    if (tid >= PIX/4) return;
    int b  = tid / (HW/4);
    int r4 = tid % (HW/4);
    int r  = r4 * 4;
    const float4* xp = (const float4*)(x + (size_t)b*CHW) + r4;
    unsigned lo0=0, lo1=0, lo2=0, lo3=0, hi0=0, hi1=0, hi2=0, hi3=0;
    bool anyzero = false;
    #pragma unroll 8
    for (int c = 0; c < Cc; c++) {
        float bb = __ldg(bias0 + c);
        float4 v = __ldg(xp + (size_t)c*(HW/4));
        v.x += bb; v.y += bb; v.z += bb; v.w += bb;
        anyzero |= (v.x == 0.f) | (v.y == 0.f) | (v.z == 0.f) | (v.w == 0.f);
        unsigned b0 = (v.x < 0.f), b1 = (v.y < 0.f), b2 = (v.z < 0.f), b3 = (v.w < 0.f);
        if (c < 32) { lo0 |= b0 << c; lo1 |= b1 << c; lo2 |= b2 << c; lo3 |= b3 << c; }
        else { int s = c-32; hi0 |= b0 << s; hi1 |= b1 << s; hi2 |= b2 << s; hi3 |= b3 << s; }
    }
    if (anyzero) {  // rare exact-zero: queue exact indices for fixup
        for (int c = 0; c < Cc; c++) {
            float bb = __ldg(bias0 + c);
            float4 v = __ldg(xp + (size_t)c*(HW/4));
            float vv[4] = {v.x+bb, v.y+bb, v.z+bb, v.w+bb};
            for (int k = 0; k < 4; k++)
                if (vv[k] == 0.f) {
                    int s = atomicAdd(&g_zero_cnt, 1);
                    if (s < 4096) g_zero_list[s] = b*CHW + c*HW + (r+k);
                }
        }
    }
    int h = r / Ww, w_ = r % Ww;   // 4 pixels are in the same row (Ww % 4 == 0)
    unsigned long long* dst = g_amask + b*PADHW + (h+1)*PADW + (w_+1);
    dst[0] = (unsigned long long)lo0 | ((unsigned long long)hi0 << 32);
    dst[1] = (unsigned long long)lo1 | ((unsigned long long)hi1 << 32);
    dst[2] = (unsigned long long)lo2 | ((unsigned long long)hi2 << 32);
    dst[3] = (unsigned long long)lo3 | ((unsigned long long)hi3 << 32);
}

// ---------------- conv: popcount ternary conv + fused epilogue ----------------
// Block = 4 warps; warp = psub (16 output channels), lane = pixel-quad.
// All weight/epi shared loads are warp-uniform; residual I/O fully coalesced.
__global__ __launch_bounds__(128, 4)
void conv_kernel(const float* __restrict__ x, float* __restrict__ out) {
    __shared__ uint4  s_wm[Pp*9];
    __shared__ float  s_basef[9*Pp];
    __shared__ float4 s_epi[Pp];
    for (int i = threadIdx.x; i < Pp*9; i += blockDim.x) s_wm[i]    = g_wm[i];
    for (int i = threadIdx.x; i < 9*Pp; i += blockDim.x) s_basef[i] = g_basef[i];
    for (int i = threadIdx.x; i < Pp;   i += blockDim.x) s_epi[i]   = g_epi[i];
    __syncthreads();

    int lane = threadIdx.x & 31;
    int psub = threadIdx.x >> 5;            // warp id = output-channel subset
    int g    = blockIdx.x * 32 + lane;      // pixel-quad (grid exact: 1568*32 = GROUPS)
    int b  = g / (Hh*GPR);
    int r  = g % (Hh*GPR);
    int h  = r / GPR;
    int w0 = (r % GPR) * NPIX;

    // 3 rows x 6 cols of padded neighbor masks (covers 4 output pixels)
    unsigned long long m[3][6];
    const unsigned long long* am = g_amask + b*PADHW;
    #pragma unroll
    for (int ri = 0; ri < 3; ri++)
        #pragma unroll
        for (int ci = 0; ci < 6; ci++)
            m[ri][ci] = __ldg(am + (h+ri)*PADW + (w0+ci));

    int ch    = (h == 0) ? 0 : ((h == Hh-1) ? 2 : 1);
    int caseM = ch*3 + 1;
    int caseL = ch*3 + ((w0 == 0) ? 0 : 1);
    int caseR = ch*3 + ((w0 + NPIX - 1 == Ww-1) ? 2 : 1);

    size_t obase = (size_t)b*CHW + (size_t)h*Ww + w0;
    int p0 = psub * PPT;

    float4 res = __ldg((const float4*)(x + obase + (size_t)p0*HW));  // prefetch p0

    #pragma unroll 2
    for (int i = 0; i < PPT; i++) {
        int p = p0 + i;
        // prefetch next residual before the popc block
        float4 resn;
        if (i < PPT-1) resn = __ldg((const float4*)(x + obase + (size_t)(p+1)*HW));

        int acc0 = 0, acc1 = 0, acc2 = 0, acc3 = 0;
        #pragma unroll
        for (int t = 0; t < 9; t++) {
            uint4 wv = s_wm[p*9 + t];     // warp-uniform address
            const int ri = t / 3, ci = t % 3;
            {
                unsigned long long sa = m[ri][ci+0];
                acc0 += __popc(((unsigned)sa ^ wv.x) & wv.z)
                      + __popc(((unsigned)(sa>>32) ^ wv.y) & wv.w);
            }
            {
                unsigned long long sa = m[ri][ci+1];
                acc1 += __popc(((unsigned)sa ^ wv.x) & wv.z)
                      + __popc(((unsigned)(sa>>32) ^ wv.y) & wv.w);
            }
            {
                unsigned long long sa = m[ri][ci+2];
                acc2 += __popc(((unsigned)sa ^ wv.x) & wv.z)
                      + __popc(((unsigned)(sa>>32) ^ wv.y) & wv.w);
            }
            {
                unsigned long long sa = m[ri][ci+3];
                acc3 += __popc(((unsigned)sa ^ wv.x) & wv.z)
                      + __popc(((unsigned)(sa>>32) ^ wv.y) & wv.w);
            }
        }
        float4 e = s_epi[p];
        float A2 = 2.0f * e.x;
        float bM = fmaf(s_basef[caseM*Pp + p], -e.x, e.y);
        float bL = fmaf(s_basef[caseL*Pp + p], -e.x, e.y);
        float bR = fmaf(s_basef[caseR*Pp + p], -e.x, e.y);

        float4 o; float v;
        v = fmaf((float)acc0, A2, bL) + res.x; o.x = (v >= 0.f ? v : v*e.z) + e.w;
        v = fmaf((float)acc1, A2, bM) + res.y; o.y = (v >= 0.f ? v : v*e.z) + e.w;
        v = fmaf((float)acc2, A2, bM) + res.z; o.z = (v >= 0.f ? v : v*e.z) + e.w;
        v = fmaf((float)acc3, A2, bR) + res.w; o.w = (v >= 0.f ? v : v*e.z) + e.w;
        *(float4*)(out + obase + (size_t)p*HW) = o;
        res = resn;
    }
}

// ---------------- fixup: exact recompute for exact-zero activations ----------------
__global__ void fixup_kernel(const float* __restrict__ x,
                             const float* __restrict__ bias0,
                             const float* __restrict__ w,
                             float* __restrict__ out) {
    int cnt = g_zero_cnt;
    if (cnt > 4096) cnt = 4096;
    int nitems = cnt * 9 * Pp;
    for (int it = blockIdx.x*blockDim.x + threadIdx.x; it < nitems;
         it += gridDim.x*blockDim.x) {
        int zi  = it / (9*Pp);
        int rem = it % (9*Pp);
        int d   = rem / Pp;
        int p   = rem % Pp;
        int z   = g_zero_list[zi];
        int b   = z / CHW;
        int zr  = (z % CHW) % HW;
        int zh  = zr / Ww, zw = zr % Ww;
        int oh  = zh + (d/3) - 1;
        int ow  = zw + (d%3) - 1;
        if (oh < 0 || oh >= Hh || ow < 0 || ow >= Ww) continue;

        float conv = 0.f;
        const float* wp = w + p*(Cc*9);
        for (int c = 0; c < Cc; c++) {
            const float* xc = x + (size_t)b*CHW + (size_t)c*HW;
            float b0 = bias0[c];
            #pragma unroll
            for (int t = 0; t < 9; t++) {
                int ih = oh + t/3 - 1, iw = ow + t%3 - 1;
                if (ih < 0 || ih >= Hh || iw < 0 || iw >= Ww) continue;
                float v  = xc[ih*Ww + iw] + b0;
                float a  = (v  > 0.f) ? 1.f : ((v  < 0.f) ? -1.f : 0.f);
                float wv = wp[c*9 + t];
                float ws = (wv > 0.f) ? 1.f : ((wv < 0.f) ? -1.f : 0.f);
                conv += a * ws;
            }
        }
        float4 e = g_epi[p];
        size_t oi = (size_t)b*CHW + (size_t)p*HW + (size_t)oh*Ww + ow;
        float val = fmaf(conv, e.x, e.y) + x[oi];
        val = (val >= 0.f ? val : val*e.z) + e.w;
        out[oi] = val;
    }
}

// ---------------- launch ----------------
extern "C" void kernel_launch(void* const* d_in, const int* in_sizes, int n_in,
                              void* d_out, int out_size) {
    const float* x     = (const float*)d_in[0];
    const float* bias0 = (const float*)d_in[1];
    const float* w     = (const float*)d_in[2];
    const float* gamma = (const float*)d_in[3];
    const float* beta  = (const float*)d_in[4];
    const float* rmean = (const float*)d_in[5];
    const float* rvar  = (const float*)d_in[6];
    const float* bias1 = (const float*)d_in[7];
    const float* alpha = (const float*)d_in[8];
    const float* bias2 = (const float*)d_in[9];
    float* out = (float*)d_out;

    prep_kernel<<<Pp, 64>>>(w, gamma, beta, rmean, rvar, bias1, alpha, bias2);
    binarize_kernel<<<(PIX/4 + 255)/256, 256>>>(x, bias0);
    conv_kernel<<<GROUPS/32, 128>>>(x, out);
    fixup_kernel<<<64, 128>>>(x, bias0, w, out);
}